// round 12
// baseline (speedup 1.0000x reference)
#include <cuda_runtime.h>
#include <cstdint>
#include <cstddef>

// Router: top-1 MoE routing with capacity constraint.
// Outputs (float32): dispatch[N,8,Ccap], combine[N,8,Ccap], z, aux, div, std
//
// Single stream, 3 nodes, PDL-chained (R11 champion + balanced hybrid):
//   1) hybrid_kernel (160 blocks, 2 phases, all blocks busy in both):
//      A: token t -> thread 5t (spread over 160 SMs), keys+buckets+partials
//      B: flag-sync, then all 1280 warps rank ~6.4 tokens each (bucket scan)
//      Triggers PDL at entry -> fill starts immediately.
//   2) fill_kernel: pristine 805MB zero fill (16 regs, DRAM roofline).
//   3) scatter_kernel: PDL secondary; prologue overlaps fill tail; gridsync;
//      <=16K sparse stores + scalars + counter reset.

#define E 8
#define MAXN 8192
#define NACC 55   // 0:z  1..8:psum  9..16:cnt  17..52:G(upper tri 36)  53:sum  54:sumsq
#define HBLOCKS 160
#define SPREAD 5          // token t handled by global thread 5*t (40960 threads)
#define FBLOCKS 2368

__device__ unsigned long long g_fkey[MAXN];        // [e:3][p_bits:32][invidx:13]
__device__ unsigned long long g_bucket[E][MAXN];   // keys grouped by expert
__device__ int   g_bucket_cnt[E];                  // reset by scatter
__device__ float g_prob[MAXN];
__device__ int   g_rank[MAXN];
__device__ float g_part[HBLOCKS][NACC];
__device__ int   g_tok_done  = 0;                  // reset by scatter
__device__ int   g_rank_done = 0;                  // reset by scatter

// ------------------------------------------------------ hybrid: token+rank ----
__global__ void hybrid_kernel(const float* __restrict__ logits, int N) {
#if __CUDA_ARCH__ >= 900
    cudaTriggerProgrammaticLaunchCompletion();   // let the fill launch NOW
#endif
    const int bid = blockIdx.x;
    const int tid = threadIdx.x;
    const int lane = tid & 31;
    const int wid  = tid >> 5;
    const int g    = bid * blockDim.x + tid;

    // ---------------- phase A: token (spread over all blocks) ----------------
    float vals[NACC];
#pragma unroll
    for (int k = 0; k < NACC; k++) vals[k] = 0.0f;

    int tokA = g / SPREAD;
    bool activeA = (g % SPREAD == 0) && (tokA < N);
    if (activeA) {
        int i = tokA;
        float4 r0 = reinterpret_cast<const float4*>(logits)[2 * i + 0];
        float4 r1 = reinterpret_cast<const float4*>(logits)[2 * i + 1];
        float raw[E] = {r0.x, r0.y, r0.z, r0.w, r1.x, r1.y, r1.z, r1.w};

        float l[E];
        float s = 0.f, s2 = 0.f;
#pragma unroll
        for (int j = 0; j < E; j++) {
            s  += raw[j];
            s2 += raw[j] * raw[j];
            float c = fminf(fmaxf(raw[j], -10.0f), 10.0f);
            l[j] = c / 1.5f;                 // IEEE div, matches JAX clip/temp
        }
        vals[53] = s;
        vals[54] = s2;

        float m = l[0]; int e = 0;
#pragma unroll
        for (int j = 1; j < E; j++) {
            if (l[j] > m) { m = l[j]; e = j; }
        }

        float sumexp = 0.f;
        float ex[E];
#pragma unroll
        for (int j = 0; j < E; j++) { ex[j] = expf(l[j] - m); sumexp += ex[j]; }
#pragma unroll
        for (int j = 0; j < E; j++) vals[1 + j] = ex[j] / sumexp;
#pragma unroll
        for (int j = 0; j < E; j++) vals[9 + j] = (e == j) ? 1.0f : 0.0f;

        float p = 1.0f / sumexp;             // probs[argmax] exactly as JAX
        g_prob[i] = p;
        unsigned long long key = ((unsigned long long)e << 45)
                               | ((unsigned long long)__float_as_uint(p) << 13)
                               | (unsigned long long)(unsigned)(MAXN - 1 - i);
        g_fkey[i] = key;
        int pos = atomicAdd(&g_bucket_cnt[e], 1);   // bucket order irrelevant
        g_bucket[e][pos] = key;

        float lse = m + logf(sumexp);
        vals[0] = lse * lse;

        int t = 0;
#pragma unroll
        for (int a = 0; a < E; a++)
#pragma unroll
            for (int b = a; b < E; b++) vals[17 + t++] = l[a] * l[b];
    }

    // per-block loss partial (inactive threads contribute zeros)
#pragma unroll
    for (int k = 0; k < NACC; k++) {
        float v = vals[k];
        v += __shfl_down_sync(0xffffffffu, v, 16);
        v += __shfl_down_sync(0xffffffffu, v, 8);
        v += __shfl_down_sync(0xffffffffu, v, 4);
        v += __shfl_down_sync(0xffffffffu, v, 2);
        v += __shfl_down_sync(0xffffffffu, v, 1);
        vals[k] = v;
    }
    __shared__ float sAcc[8][NACC];
    if (lane == 0) {
#pragma unroll
        for (int k = 0; k < NACC; k++) sAcc[wid][k] = vals[k];
    }
    __syncthreads();
    for (int k = tid; k < NACC; k += blockDim.x) {
        float v = 0.f;
#pragma unroll
        for (int w = 0; w < 8; w++) v += sAcc[w][k];
        g_part[bid][k] = v;
    }

    // ---------------- phase sync: all 160 blocks (wave-1 resident) ----------
    __syncthreads();
    __threadfence();
    if (tid == 0) {
        atomicAdd(&g_tok_done, 1);
        while (*((volatile int*)&g_tok_done) < HBLOCKS) __nanosleep(32);
    }
    __syncthreads();
    __threadfence();

    // ---------------- phase B: rank (all 1280 warps) ------------------------
    int w = g >> 5;                              // global warp id, 0..1279
    for (int tok = w; tok < N; tok += (HBLOCKS * 256) / 32) {
        unsigned long long key = g_fkey[tok];
        int e = (int)(key >> 45);
        int bc = g_bucket_cnt[e];
        const unsigned long long* bkt = g_bucket[e];
        int cnt = 0;
        for (int j = lane; j < bc; j += 32)
            cnt += (int)(bkt[j] > key);
        cnt += __shfl_down_sync(0xffffffffu, cnt, 16);
        cnt += __shfl_down_sync(0xffffffffu, cnt, 8);
        cnt += __shfl_down_sync(0xffffffffu, cnt, 4);
        cnt += __shfl_down_sync(0xffffffffu, cnt, 2);
        cnt += __shfl_down_sync(0xffffffffu, cnt, 1);
        if (lane == 0) g_rank[tok] = cnt;
    }

    __syncthreads();
    __threadfence();
    if (tid == 0) atomicAdd(&g_rank_done, 1);
}

// ---------------------------------------------------------------- fill ----
// PRISTINE (16 regs, no sync/atomics). PDL secondary of hybrid (no gridsync:
// no data dependency, full overlap). Triggers at entry for the scatter.
__global__ void fill_kernel(uint4* __restrict__ out, size_t n4) {
#if __CUDA_ARCH__ >= 900
    cudaTriggerProgrammaticLaunchCompletion();
#endif
    const uint4 z = make_uint4(0u, 0u, 0u, 0u);
    size_t i = (size_t)blockIdx.x * blockDim.x + threadIdx.x;
    size_t stride = (size_t)gridDim.x * blockDim.x;
    for (; i < n4; i += stride) out[i] = z;
}

// -------------------------------------------------------------- scatter ----
__global__ void scatter_kernel(float* __restrict__ dispatch_out,
                               float* __restrict__ combine_out,
                               float* __restrict__ scalars_out,
                               int N, int Ccap) {
    int i = blockIdx.x * blockDim.x + threadIdx.x;

    // ---- prologue (overlaps fill tail): wait for rank, prefetch, scalars ----
    if (threadIdx.x == 0) {
        while (*((volatile int*)&g_rank_done) < HBLOCKS) __nanosleep(32);
    }
    __syncthreads();
    __threadfence();

    int rank = Ccap;
    unsigned long long key = 0;
    float p = 0.f;
    if (i < N) {
        rank = g_rank[i];
        key  = g_fkey[i];
        p    = g_prob[i];
    }

    __shared__ float sOut[4];
    if (blockIdx.x == 0) {
        __shared__ float sAccF[NACC];
        if (threadIdx.x < NACC) {
            float v = 0.f;
#pragma unroll
            for (int r = 0; r < HBLOCKS; r++) v += g_part[r][threadIdx.x];
            sAccF[threadIdx.x] = v;
        }
        __syncthreads();
        if (threadIdx.x == 0) {
            float z_loss = sAccF[0] / (float)N;

            float aux = 0.f;
            for (int e = 0; e < E; e++) aux += sAccF[9 + e] * sAccF[1 + e];
            aux = aux * (float)E / ((float)N * (float)N);

            float G[E][E];
            int t = 0;
            for (int a = 0; a < E; a++)
                for (int b = a; b < E; b++) { G[a][b] = sAccF[17 + t]; G[b][a] = sAccF[17 + t]; t++; }
            float nrm[E];
            for (int a = 0; a < E; a++) nrm[a] = fmaxf(sqrtf(G[a][a]), 1e-12f);
            float div = 0.f;
            for (int a = 0; a < E; a++)
                for (int b = a + 1; b < E; b++) {
                    float c = G[a][b] / (nrm[a] * nrm[b]);
                    div += 2.0f * c * c;
                }
            div /= (float)(E * (E - 1));

            double M = (double)N * E;
            double sm = (double)sAccF[53], sq = (double)sAccF[54];
            double var = (sq - sm * sm / M) / (M - 1.0);

            sOut[0] = z_loss;
            sOut[1] = aux;
            sOut[2] = div;
            sOut[3] = (float)sqrt(var);
        }
        __syncthreads();
    }

    // ---- wait for fill completion before touching d_out ----
#if __CUDA_ARCH__ >= 900
    cudaGridDependencySynchronize();
#endif

    if (i < N && rank < Ccap) {
        int e = (int)(key >> 45);
        size_t b = ((size_t)i * E + e) * (size_t)Ccap + (size_t)rank;
        dispatch_out[b] = 1.0f;
        combine_out[b]  = p;
    }
    if (blockIdx.x == 0 && threadIdx.x < 4)
        scalars_out[threadIdx.x] = sOut[threadIdx.x];

    // reset counters for next (identical) call
    if (i < E)  g_bucket_cnt[i] = 0;
    if (i == E) g_tok_done = 0;
    if (i == E + 1) g_rank_done = 0;
}

// -------------------------------------------------------------- launch ----
extern "C" void kernel_launch(void* const* d_in, const int* in_sizes, int n_in,
                              void* d_out, int out_size) {
    const float* logits = (const float*)d_in[1];
    int N = in_sizes[1] / E;                              // 8192
    int Ccap = (int)((3 * N + 2 * E - 1) / (2 * E));      // ceil(1.5*N/E) = 1536
    if (Ccap < 1) Ccap = 1;

    float* out = (float*)d_out;
    size_t D = (size_t)N * E * (size_t)Ccap;
    float* dispatch_out = out;
    float* combine_out  = out + D;
    float* scalars_out  = out + 2 * D;

    size_t n4 = (size_t)out_size >> 2;

    cudaLaunchAttribute pdl[1];
    pdl[0].id = cudaLaunchAttributeProgrammaticStreamSerialization;
    pdl[0].val.programmaticStreamSerializationAllowed = 1;

    // 1) hybrid: balanced token+rank (triggers at entry so the fill overlaps)
    hybrid_kernel<<<HBLOCKS, 256>>>(logits, N);

    // 2) fill: PDL secondary (launches immediately; no gridsync inside)
    {
        cudaLaunchConfig_t cfg = {};
        cfg.gridDim  = dim3(FBLOCKS, 1, 1);
        cfg.blockDim = dim3(256, 1, 1);
        cfg.stream   = 0;
        cfg.attrs    = pdl;
        cfg.numAttrs = 1;
        cudaLaunchKernelEx(&cfg, fill_kernel, (uint4*)d_out, n4);
    }
    size_t rem = (size_t)out_size & 3;
    if (rem) cudaMemsetAsync((float*)d_out + (out_size - rem), 0, rem * sizeof(float));

    // 3) scatter: PDL secondary of fill (prologue overlaps fill tail)
    {
        cudaLaunchConfig_t cfg = {};
        cfg.gridDim  = dim3((N + 255) / 256, 1, 1);
        cfg.blockDim = dim3(256, 1, 1);
        cfg.stream   = 0;
        cfg.attrs    = pdl;
        cfg.numAttrs = 1;
        cudaLaunchKernelEx(&cfg, scatter_kernel,
                           dispatch_out, combine_out, scalars_out, N, Ccap);
    }
}

// round 14
// speedup vs baseline: 1.0937x; 1.0937x over previous
#include <cuda_runtime.h>
#include <cstdint>
#include <cstddef>

// Router: top-1 MoE routing with capacity constraint.
// Outputs (float32): dispatch[N,8,Ccap], combine[N,8,Ccap], z, aux, div, std
//
// R11 topology (single stream, 3 nodes, PDL-chained) + work-stealing fill:
//   1) hybrid_kernel (160 blocks): token (0-31) + spin-then-rank (32-159);
//      triggers PDL at entry -> fill starts immediately.
//   2) fill_kernel: WORK-STEALING 805MB zero fill (stagger-immune, 32KB chunks);
//      triggers at entry for scatter. No cross-kernel waits inside.
//   3) scatter_kernel: PDL secondary; prologue (rank spin, loads, scalars)
//      overlaps fill tail; cudaGridDependencySynchronize(); sparse stores;
//      counter reset (incl. g_fill_next) strictly post-gridsync.

#define E 8
#define MAXN 8192
#define NACC 55   // 0:z  1..8:psum  9..16:cnt  17..52:G(upper tri 36)  53:sum  54:sumsq
#define TBLOCKS 32
#define RBLOCKS 128
#define HBLOCKS (TBLOCKS + RBLOCKS)
#define FBLOCKS 2368
#define CHUNK   2048ull      // uint4 per grab = 32KB

__device__ unsigned long long g_fkey[MAXN];        // [e:3][p_bits:32][invidx:13]
__device__ unsigned long long g_bucket[E][MAXN];   // keys grouped by expert
__device__ int   g_bucket_cnt[E];                  // reset by scatter
__device__ float g_prob[MAXN];
__device__ int   g_rank[MAXN];
__device__ float g_part[TBLOCKS][NACC];
__device__ int   g_tok_done  = 0;                  // reset by scatter
__device__ int   g_rank_done = 0;                  // reset by scatter
__device__ unsigned long long g_fill_next = 0ull;  // reset by scatter

// ------------------------------------------------------ hybrid: token+rank ----
// 160 blocks, all wave-1 resident -> internal spin (rank waits token) is safe.
__global__ void hybrid_kernel(const float* __restrict__ logits, int N) {
#if __CUDA_ARCH__ >= 900
    cudaTriggerProgrammaticLaunchCompletion();   // let the fill launch NOW
#endif
    const int bid = blockIdx.x;
    const int tid = threadIdx.x;
    const int lane = tid & 31;
    const int wid  = tid >> 5;

    if (bid < TBLOCKS) {
        // ---------------- token path ----------------
        int i = bid * blockDim.x + tid;
        float vals[NACC];
#pragma unroll
        for (int k = 0; k < NACC; k++) vals[k] = 0.0f;

        if (i < N) {
            float4 r0 = reinterpret_cast<const float4*>(logits)[2 * i + 0];
            float4 r1 = reinterpret_cast<const float4*>(logits)[2 * i + 1];
            float raw[E] = {r0.x, r0.y, r0.z, r0.w, r1.x, r1.y, r1.z, r1.w};

            float l[E];
            float s = 0.f, s2 = 0.f;
#pragma unroll
            for (int j = 0; j < E; j++) {
                s  += raw[j];
                s2 += raw[j] * raw[j];
                float c = fminf(fmaxf(raw[j], -10.0f), 10.0f);
                l[j] = c / 1.5f;                 // IEEE div, matches JAX clip/temp
            }
            vals[53] = s;
            vals[54] = s2;

            float m = l[0]; int e = 0;
#pragma unroll
            for (int j = 1; j < E; j++) {
                if (l[j] > m) { m = l[j]; e = j; }
            }

            float sumexp = 0.f;
            float ex[E];
#pragma unroll
            for (int j = 0; j < E; j++) { ex[j] = expf(l[j] - m); sumexp += ex[j]; }
#pragma unroll
            for (int j = 0; j < E; j++) vals[1 + j] = ex[j] / sumexp;
#pragma unroll
            for (int j = 0; j < E; j++) vals[9 + j] = (e == j) ? 1.0f : 0.0f;

            float p = 1.0f / sumexp;             // probs[argmax] exactly as JAX
            g_prob[i] = p;
            unsigned long long key = ((unsigned long long)e << 45)
                                   | ((unsigned long long)__float_as_uint(p) << 13)
                                   | (unsigned long long)(unsigned)(MAXN - 1 - i);
            g_fkey[i] = key;
            int pos = atomicAdd(&g_bucket_cnt[e], 1);   // bucket order irrelevant
            g_bucket[e][pos] = key;

            float lse = m + logf(sumexp);
            vals[0] = lse * lse;

            int t = 0;
#pragma unroll
            for (int a = 0; a < E; a++)
#pragma unroll
                for (int b = a; b < E; b++) vals[17 + t++] = l[a] * l[b];
        }

#pragma unroll
        for (int k = 0; k < NACC; k++) {
            float v = vals[k];
            v += __shfl_down_sync(0xffffffffu, v, 16);
            v += __shfl_down_sync(0xffffffffu, v, 8);
            v += __shfl_down_sync(0xffffffffu, v, 4);
            v += __shfl_down_sync(0xffffffffu, v, 2);
            v += __shfl_down_sync(0xffffffffu, v, 1);
            vals[k] = v;
        }
        __shared__ float sAcc[8][NACC];
        if (lane == 0) {
#pragma unroll
            for (int k = 0; k < NACC; k++) sAcc[wid][k] = vals[k];
        }
        __syncthreads();
        for (int k = tid; k < NACC; k += blockDim.x) {
            float v = 0.f;
#pragma unroll
            for (int w = 0; w < 8; w++) v += sAcc[w][k];
            g_part[bid][k] = v;
        }
        __syncthreads();
        __threadfence();
        if (tid == 0) atomicAdd(&g_tok_done, 1);
        return;
    }

    // ---------------- rank path: spin, then bucketed count ----------------
    if (tid == 0) {
        while (*((volatile int*)&g_tok_done) < TBLOCKS) __nanosleep(64);
    }
    __syncthreads();
    __threadfence();

    int base = ((bid - TBLOCKS) * 8 + wid) * 8;   // 8 tokens per warp

#pragma unroll
    for (int t = 0; t < 8; t++) {
        int tok = base + t;
        if (tok >= N) break;
        unsigned long long key = g_fkey[tok];
        int e = (int)(key >> 45);
        int bc = g_bucket_cnt[e];
        const unsigned long long* bkt = g_bucket[e];
        int cnt = 0;
        for (int j = lane; j < bc; j += 32)
            cnt += (int)(bkt[j] > key);
        cnt += __shfl_down_sync(0xffffffffu, cnt, 16);
        cnt += __shfl_down_sync(0xffffffffu, cnt, 8);
        cnt += __shfl_down_sync(0xffffffffu, cnt, 4);
        cnt += __shfl_down_sync(0xffffffffu, cnt, 2);
        cnt += __shfl_down_sync(0xffffffffu, cnt, 1);
        if (lane == 0) g_rank[tok] = cnt;
    }

    __syncthreads();
    __threadfence();
    if (tid == 0) atomicAdd(&g_rank_done, 1);
}

// ---------------------------------------------------------------- fill ----
// Work-stealing zero fill: late-starting blocks simply grab fewer chunks, so
// the completion tail is one chunk (~6us) regardless of start stagger.
__global__ void fill_kernel(uint4* __restrict__ out, size_t n4) {
#if __CUDA_ARCH__ >= 900
    cudaTriggerProgrammaticLaunchCompletion();
#endif
    __shared__ unsigned long long sBase;
    const int tid = threadIdx.x;
    const uint4 z = make_uint4(0u, 0u, 0u, 0u);

    for (;;) {
        if (tid == 0) sBase = atomicAdd(&g_fill_next, CHUNK);
        __syncthreads();
        unsigned long long base = sBase;      // uniform across block
        if (base >= (unsigned long long)n4) break;
        unsigned long long end = base + CHUNK;
        if (end > (unsigned long long)n4) end = (unsigned long long)n4;
        for (unsigned long long j = base + tid; j < end; j += 256ull)
            out[j] = z;
        __syncthreads();                      // all read sBase before overwrite
    }
}

// -------------------------------------------------------------- scatter ----
__global__ void scatter_kernel(float* __restrict__ dispatch_out,
                               float* __restrict__ combine_out,
                               float* __restrict__ scalars_out,
                               int N, int Ccap) {
    int i = blockIdx.x * blockDim.x + threadIdx.x;

    // ---- prologue (overlaps fill tail): wait for rank, prefetch, scalars ----
    if (threadIdx.x == 0) {
        while (*((volatile int*)&g_rank_done) < RBLOCKS) __nanosleep(32);
    }
    __syncthreads();
    __threadfence();

    int rank = Ccap;
    unsigned long long key = 0;
    float p = 0.f;
    if (i < N) {
        rank = g_rank[i];
        key  = g_fkey[i];
        p    = g_prob[i];
    }

    __shared__ float sOut[4];
    if (blockIdx.x == 0) {
        __shared__ float sAccF[NACC];
        if (threadIdx.x < NACC) {
            float v = 0.f;
#pragma unroll
            for (int r = 0; r < TBLOCKS; r++) v += g_part[r][threadIdx.x];
            sAccF[threadIdx.x] = v;
        }
        __syncthreads();
        if (threadIdx.x == 0) {
            float z_loss = sAccF[0] / (float)N;

            float aux = 0.f;
            for (int e = 0; e < E; e++) aux += sAccF[9 + e] * sAccF[1 + e];
            aux = aux * (float)E / ((float)N * (float)N);

            float G[E][E];
            int t = 0;
            for (int a = 0; a < E; a++)
                for (int b = a; b < E; b++) { G[a][b] = sAccF[17 + t]; G[b][a] = sAccF[17 + t]; t++; }
            float nrm[E];
            for (int a = 0; a < E; a++) nrm[a] = fmaxf(sqrtf(G[a][a]), 1e-12f);
            float div = 0.f;
            for (int a = 0; a < E; a++)
                for (int b = a + 1; b < E; b++) {
                    float c = G[a][b] / (nrm[a] * nrm[b]);
                    div += 2.0f * c * c;
                }
            div /= (float)(E * (E - 1));

            double M = (double)N * E;
            double sm = (double)sAccF[53], sq = (double)sAccF[54];
            double var = (sq - sm * sm / M) / (M - 1.0);

            sOut[0] = z_loss;
            sOut[1] = aux;
            sOut[2] = div;
            sOut[3] = (float)sqrt(var);
        }
        __syncthreads();
    }

    // ---- wait for fill completion (backward-pointing dependency only) ----
#if __CUDA_ARCH__ >= 900
    cudaGridDependencySynchronize();
#endif

    if (i < N && rank < Ccap) {
        int e = (int)(key >> 45);
        size_t b = ((size_t)i * E + e) * (size_t)Ccap + (size_t)rank;
        dispatch_out[b] = 1.0f;
        combine_out[b]  = p;
    }
    if (blockIdx.x == 0 && threadIdx.x < 4)
        scalars_out[threadIdx.x] = sOut[threadIdx.x];

    // reset counters for next (identical) call — fill provably done here
    if (i < E)  g_bucket_cnt[i] = 0;
    if (i == E) g_tok_done = 0;
    if (i == E + 1) g_rank_done = 0;
    if (i == E + 2) g_fill_next = 0ull;
}

// -------------------------------------------------------------- launch ----
extern "C" void kernel_launch(void* const* d_in, const int* in_sizes, int n_in,
                              void* d_out, int out_size) {
    const float* logits = (const float*)d_in[1];
    int N = in_sizes[1] / E;                              // 8192
    int Ccap = (int)((3 * N + 2 * E - 1) / (2 * E));      // ceil(1.5*N/E) = 1536
    if (Ccap < 1) Ccap = 1;

    float* out = (float*)d_out;
    size_t D = (size_t)N * E * (size_t)Ccap;
    float* dispatch_out = out;
    float* combine_out  = out + D;
    float* scalars_out  = out + 2 * D;

    size_t n4 = (size_t)out_size >> 2;

    cudaLaunchAttribute pdl[1];
    pdl[0].id = cudaLaunchAttributeProgrammaticStreamSerialization;
    pdl[0].val.programmaticStreamSerializationAllowed = 1;

    // 1) hybrid: token + rank (triggers at entry so the fill overlaps it)
    hybrid_kernel<<<HBLOCKS, 256>>>(logits, N);

    // 2) fill: PDL secondary (launches immediately; work-stealing inside)
    {
        cudaLaunchConfig_t cfg = {};
        cfg.gridDim  = dim3(FBLOCKS, 1, 1);
        cfg.blockDim = dim3(256, 1, 1);
        cfg.stream   = 0;
        cfg.attrs    = pdl;
        cfg.numAttrs = 1;
        cudaLaunchKernelEx(&cfg, fill_kernel, (uint4*)d_out, n4);
    }
    size_t rem = (size_t)out_size & 3;
    if (rem) cudaMemsetAsync((float*)d_out + (out_size - rem), 0, rem * sizeof(float));

    // 3) scatter: PDL secondary of fill (prologue overlaps fill tail)
    {
        cudaLaunchConfig_t cfg = {};
        cfg.gridDim  = dim3((N + 255) / 256, 1, 1);
        cfg.blockDim = dim3(256, 1, 1);
        cfg.stream   = 0;
        cfg.attrs    = pdl;
        cfg.numAttrs = 1;
        cudaLaunchKernelEx(&cfg, scatter_kernel,
                           dispatch_out, combine_out, scalars_out, N, Ccap);
    }
}